// round 1
// baseline (speedup 1.0000x reference)
#include <cuda_runtime.h>
#include <cuda_bf16.h>
#include <cstdint>

// Problem constants (fixed shapes)
constexpr int IN_F  = 4096;
constexpr int OUT_F = 4096;
constexpr int M_TOT = 4 * 2048;          // 8192 rows of activations
constexpr int NB    = (OUT_F / 16) * (IN_F / 16);  // 65536 tiles

// Scratch (static __device__ arrays — no allocation allowed)
__device__ float g_x[(size_t)M_TOT * IN_F];      // Hadamard-rotated activations (134 MB)
__device__ float g_W[(size_t)OUT_F * IN_F];      // decoded weights (67 MB)

// ---------------------------------------------------------------------------
// Kernel 1: per-128-group Walsh-Hadamard transform (Sylvester H, normalized).
// One warp per 128-element group; each lane holds 4 contiguous elements.
// ---------------------------------------------------------------------------
__global__ void __launch_bounds__(256) fwht_kernel(const float* __restrict__ in,
                                                   float* __restrict__ out) {
    const int warp = (blockIdx.x << 3) | (threadIdx.x >> 5);   // group index
    const int lane = threadIdx.x & 31;
    const size_t base = (size_t)warp * 128;

    float4 v = reinterpret_cast<const float4*>(in + base)[lane];
    float a = v.x, b = v.y, c = v.z, d = v.w;
    float t;
    // distance 1: (e0,e1), (e2,e3)
    t = a; a = a + b; b = t - b;
    t = c; c = c + d; d = t - d;
    // distance 2: (e0,e2), (e1,e3)
    t = a; a = a + c; c = t - c;
    t = b; b = b + d; d = t - d;
    // distances 4..64 via xor shuffles (mask 1..16)
    #pragma unroll
    for (int mask = 1; mask <= 16; mask <<= 1) {
        float oa = __shfl_xor_sync(0xFFFFFFFFu, a, mask);
        float ob = __shfl_xor_sync(0xFFFFFFFFu, b, mask);
        float oc = __shfl_xor_sync(0xFFFFFFFFu, c, mask);
        float od = __shfl_xor_sync(0xFFFFFFFFu, d, mask);
        const bool hi = (lane & mask) != 0;
        a = hi ? (oa - a) : (a + oa);
        b = hi ? (ob - b) : (b + ob);
        c = hi ? (oc - c) : (c + oc);
        d = hi ? (od - d) : (d + od);
    }
    const float s = 0.08838834764831845f;  // 1/sqrt(128)
    float4 o = make_float4(a * s, b * s, c * s, d * s);
    reinterpret_cast<float4*>(out + base)[lane] = o;
}

// ---------------------------------------------------------------------------
// Kernel 2: trellis decode. One block (256 threads) per 16x16 tile.
// state t = 16-bit big-endian window at bit offset 2t (mod 512) of the
// tile's 512-bit stream (32 x 16-bit words, MSB-first per word).
// ---------------------------------------------------------------------------
__global__ void __launch_bounds__(256) decode_kernel(const int* __restrict__ trellis,
                                                     const float* __restrict__ tlut,
                                                     const float* __restrict__ scales,
                                                     float* __restrict__ W) {
    const int nb = blockIdx.x;
    const int t  = threadIdx.x;

    __shared__ uint32_t w[32];
    if (t < 32) w[t] = (uint32_t)trellis[nb * 32 + t] & 0xFFFFu;
    __syncthreads();

    const int p   = t << 1;             // bit offset
    const int i   = p >> 4;             // word index
    const int off = p & 15;             // bit offset within word
    const uint32_t s = (w[i] << 16) | w[(i + 1) & 31];
    const uint32_t state = (s >> (16 - off)) & 0xFFFFu;

    const float val = tlut[state];

    const int rb = nb >> 8;             // OUT tile row   (IN_F/16 = 256 tiles per row)
    const int cb = nb & 255;            // IN tile col
    const int tx = t >> 4;
    const int ty = t & 15;
    const int row = rb * 16 + tx;
    const int col = cb * 16 + ty;

    const float sc = scales[row * (IN_F / 128) + (col >> 7)];
    W[(size_t)row * IN_F + col] = val * sc;
}

// ---------------------------------------------------------------------------
// Kernel 3: SIMT fp32 GEMM  C[M,N] = A[M,K] @ B[N,K]^T
// 128x128 block tile, BK=16, 8x8 per thread, 256 threads.
// ---------------------------------------------------------------------------
__global__ void __launch_bounds__(256) gemm_kernel(const float* __restrict__ A,
                                                   const float* __restrict__ B,
                                                   float* __restrict__ C) {
    constexpr int K = IN_F;
    constexpr int N = OUT_F;

    __shared__ float As[16][128];
    __shared__ float Bs[16][128];

    const int bm  = blockIdx.y * 128;
    const int bn  = blockIdx.x * 128;
    const int tid = threadIdx.x;

    const int lrow = tid >> 2;           // 0..63
    const int lcol = (tid & 3) << 2;     // 0,4,8,12

    const int ty = tid >> 4;             // 0..15
    const int tx = tid & 15;             // 0..15

    const float* Ab = A + (size_t)(bm + lrow) * K + lcol;
    const float* Bb = B + (size_t)(bn + lrow) * K + lcol;

    float acc[8][8];
    #pragma unroll
    for (int i = 0; i < 8; i++)
        #pragma unroll
        for (int j = 0; j < 8; j++) acc[i][j] = 0.0f;

    for (int k0 = 0; k0 < K; k0 += 16) {
        #pragma unroll
        for (int r = 0; r < 2; r++) {
            const int row = lrow + r * 64;
            float4 va = *reinterpret_cast<const float4*>(Ab + (size_t)(r * 64) * K + k0);
            float4 vb = *reinterpret_cast<const float4*>(Bb + (size_t)(r * 64) * K + k0);
            As[lcol + 0][row] = va.x; As[lcol + 1][row] = va.y;
            As[lcol + 2][row] = va.z; As[lcol + 3][row] = va.w;
            Bs[lcol + 0][row] = vb.x; Bs[lcol + 1][row] = vb.y;
            Bs[lcol + 2][row] = vb.z; Bs[lcol + 3][row] = vb.w;
        }
        __syncthreads();

        #pragma unroll
        for (int kk = 0; kk < 16; kk++) {
            float ar[8], br[8];
            *reinterpret_cast<float4*>(&ar[0]) = *reinterpret_cast<const float4*>(&As[kk][ty * 8]);
            *reinterpret_cast<float4*>(&ar[4]) = *reinterpret_cast<const float4*>(&As[kk][ty * 8 + 4]);
            *reinterpret_cast<float4*>(&br[0]) = *reinterpret_cast<const float4*>(&Bs[kk][tx * 8]);
            *reinterpret_cast<float4*>(&br[4]) = *reinterpret_cast<const float4*>(&Bs[kk][tx * 8 + 4]);
            #pragma unroll
            for (int i = 0; i < 8; i++)
                #pragma unroll
                for (int j = 0; j < 8; j++)
                    acc[i][j] = fmaf(ar[i], br[j], acc[i][j]);
        }
        __syncthreads();
    }

    float* Cp = C + (size_t)(bm + ty * 8) * N + bn + tx * 8;
    #pragma unroll
    for (int i = 0; i < 8; i++) {
        *reinterpret_cast<float4*>(Cp + (size_t)i * N + 0) = *reinterpret_cast<float4*>(&acc[i][0]);
        *reinterpret_cast<float4*>(Cp + (size_t)i * N + 4) = *reinterpret_cast<float4*>(&acc[i][4]);
    }
}

// ---------------------------------------------------------------------------
extern "C" void kernel_launch(void* const* d_in, const int* in_sizes, int n_in,
                              void* d_out, int out_size) {
    const float* input   = (const float*)d_in[0];   // [4,2048,4096] fp32
    const int*   trellis = (const int*)  d_in[1];   // [65536,32] int32
    const float* tlut    = (const float*)d_in[2];   // [65536,1] fp32
    const float* scales  = (const float*)d_in[3];   // [131072,1] fp32
    float*       out     = (float*)d_out;           // [4,2048,4096] fp32

    float* xbuf;
    float* wbuf;
    cudaGetSymbolAddress((void**)&xbuf, g_x);
    cudaGetSymbolAddress((void**)&wbuf, g_W);

    // 1) Hadamard rotate activations: 8192*32 groups, 8 groups (warps) per block
    {
        const int groups = M_TOT * (IN_F / 128);         // 262144
        fwht_kernel<<<groups / 8, 256>>>(input, xbuf);
    }
    // 2) Decode weights
    decode_kernel<<<NB, 256>>>(trellis, tlut, scales, wbuf);
    // 3) GEMM
    {
        dim3 grid(OUT_F / 128, M_TOT / 128);             // (32, 64)
        gemm_kernel<<<grid, 256>>>(xbuf, wbuf, out);
    }
}

// round 8
// speedup vs baseline: 3.6758x; 3.6758x over previous
#include <cuda_runtime.h>
#include <cuda_bf16.h>
#include <cstdint>

// ---------------- problem constants ----------------
constexpr int IN_F  = 4096;
constexpr int OUT_F = 4096;
constexpr int M_TOT = 8192;
constexpr int NB    = (OUT_F / 16) * (IN_F / 16);   // 65536 tiles

// ---------------- GEMM tiling ----------------
constexpr int BM = 128;
constexpr int BN = 128;
constexpr int BK = 32;
constexpr int STAGES = 3;
constexpr int NK = IN_F / BK;          // 128 k-iterations
constexpr int ROWPAD = 36;             // floats per smem row (pad 32->36, conflict-free)
constexpr int TILE_FLOATS = 128 * ROWPAD;          // per operand per stage
constexpr int STAGE_FLOATS = 2 * TILE_FLOATS;      // A + B
constexpr int SMEM_TOTAL = STAGES * STAGE_FLOATS * 4;   // 110592 bytes

// ---------------- scratch ----------------
__device__ float g_x[(size_t)M_TOT * IN_F];
__device__ float g_W[(size_t)OUT_F * IN_F];

// ---------------- helpers ----------------
__device__ __forceinline__ float to_tf32_rn(float x) {
    uint32_t r;
    asm("cvt.rna.tf32.f32 %0, %1;" : "=r"(r) : "f"(x));
    return __uint_as_float(r);
}
__device__ __forceinline__ uint32_t smem_to_u32(const void* p) {
    uint32_t a;
    asm("{ .reg .u64 t; cvta.to.shared.u64 t, %1; cvt.u32.u64 %0, t; }" : "=r"(a) : "l"(p));
    return a;
}
__device__ __forceinline__ void cp_async16(uint32_t dst, const void* src) {
    asm volatile("cp.async.cg.shared.global [%0], [%1], 16;" :: "r"(dst), "l"(src) : "memory");
}
#define CP_COMMIT() asm volatile("cp.async.commit_group;" ::: "memory")
#define CP_WAIT1()  asm volatile("cp.async.wait_group 1;" ::: "memory")

__device__ __forceinline__ void mma_tf32(float* c, const uint32_t* a, const uint32_t* b) {
    asm volatile(
        "mma.sync.aligned.m16n8k8.row.col.f32.tf32.tf32.f32 "
        "{%0,%1,%2,%3}, {%4,%5,%6,%7}, {%8,%9}, {%0,%1,%2,%3};"
        : "+f"(c[0]), "+f"(c[1]), "+f"(c[2]), "+f"(c[3])
        : "r"(a[0]), "r"(a[1]), "r"(a[2]), "r"(a[3]), "r"(b[0]), "r"(b[1]));
}

// ---------------------------------------------------------------------------
// Kernel 1: per-128 FWHT (Hadamard rotate), output rounded to tf32 grid
// ---------------------------------------------------------------------------
__global__ void __launch_bounds__(256) fwht_kernel(const float* __restrict__ in,
                                                   float* __restrict__ out) {
    const int warp = (blockIdx.x << 3) | (threadIdx.x >> 5);
    const int lane = threadIdx.x & 31;
    const size_t base = (size_t)warp * 128;

    float4 v = reinterpret_cast<const float4*>(in + base)[lane];
    float a = v.x, b = v.y, c = v.z, d = v.w, t;
    t = a; a = a + b; b = t - b;
    t = c; c = c + d; d = t - d;
    t = a; a = a + c; c = t - c;
    t = b; b = b + d; d = t - d;
    #pragma unroll
    for (int mask = 1; mask <= 16; mask <<= 1) {
        float oa = __shfl_xor_sync(0xFFFFFFFFu, a, mask);
        float ob = __shfl_xor_sync(0xFFFFFFFFu, b, mask);
        float oc = __shfl_xor_sync(0xFFFFFFFFu, c, mask);
        float od = __shfl_xor_sync(0xFFFFFFFFu, d, mask);
        const bool hi = (lane & mask) != 0;
        a = hi ? (oa - a) : (a + oa);
        b = hi ? (ob - b) : (b + ob);
        c = hi ? (oc - c) : (c + oc);
        d = hi ? (od - d) : (d + od);
    }
    const float s = 0.08838834764831845f;
    float4 o = make_float4(to_tf32_rn(a * s), to_tf32_rn(b * s),
                           to_tf32_rn(c * s), to_tf32_rn(d * s));
    reinterpret_cast<float4*>(out + base)[lane] = o;
}

// ---------------------------------------------------------------------------
// Kernel 2: trellis decode, output rounded to tf32 grid
// ---------------------------------------------------------------------------
__global__ void __launch_bounds__(256) decode_kernel(const int* __restrict__ trellis,
                                                     const float* __restrict__ tlut,
                                                     const float* __restrict__ scales,
                                                     float* __restrict__ W) {
    const int nb = blockIdx.x;
    const int t  = threadIdx.x;

    __shared__ uint32_t w[32];
    if (t < 32) w[t] = (uint32_t)trellis[nb * 32 + t] & 0xFFFFu;
    __syncthreads();

    const int p   = t << 1;
    const int i   = p >> 4;
    const int off = p & 15;
    const uint32_t s = (w[i] << 16) | w[(i + 1) & 31];
    const uint32_t state = (s >> (16 - off)) & 0xFFFFu;

    const float val = tlut[state];

    const int rb = nb >> 8;
    const int cb = nb & 255;
    const int tx = t >> 4;
    const int ty = t & 15;
    const int row = rb * 16 + tx;
    const int col = cb * 16 + ty;

    const float sc = scales[row * (IN_F / 128) + (col >> 7)];
    W[(size_t)row * IN_F + col] = to_tf32_rn(val * sc);
}

// ---------------------------------------------------------------------------
// Kernel 3: tf32 mma.sync GEMM  C[M,N] = A[M,K] @ B[N,K]^T
// 128x128 CTA tile, BK=32, 3-stage cp.async pipeline, 8 warps x (64x32).
// ---------------------------------------------------------------------------
__global__ void __launch_bounds__(256) gemm_mma_kernel(const float* __restrict__ A,
                                                       const float* __restrict__ B,
                                                       float* __restrict__ C) {
    extern __shared__ float smem[];   // [STAGES][2][128][ROWPAD]
    const uint32_t sbase = smem_to_u32(smem);

    const int tid  = threadIdx.x;
    const int lane = tid & 31;
    const int warp = tid >> 5;
    const int warp_m = warp >> 2;          // 0..1  -> 64-row slice
    const int warp_n = warp & 3;           // 0..3  -> 32-col slice

    // block swizzle: supertiles of 16 m-tiles x 32 n-tiles (L2 locality)
    const int bid    = blockIdx.x;
    const int group  = bid >> 9;           // / 512
    const int within = bid & 511;
    const int bm = ((group << 4) | (within & 15)) * BM;
    const int bn = (within >> 4) * BN;

    // global load assignment: 16B chunks; thread -> (row, 4-float col chunk)
    const int lrow = tid >> 3;             // 0..31
    const int lcol = (tid & 7) << 2;       // 0,4,...,28

    const float* Ag = A + (size_t)(bm + lrow) * IN_F + lcol;
    const float* Bg = B + (size_t)(bn + lrow) * IN_F + lcol;

    auto load_stage = [&](int buf, int kt) {
        const uint32_t sA = sbase + (uint32_t)(buf * STAGE_FLOATS) * 4;
        const uint32_t sB = sA + (uint32_t)TILE_FLOATS * 4;
        const int koff = kt * BK;
        #pragma unroll
        for (int r = 0; r < 4; r++) {
            const int row = lrow + (r << 5);
            cp_async16(sA + (uint32_t)(row * ROWPAD + lcol) * 4,
                       Ag + (size_t)(r << 5) * IN_F + koff);
            cp_async16(sB + (uint32_t)(row * ROWPAD + lcol) * 4,
                       Bg + (size_t)(r << 5) * IN_F + koff);
        }
    };

    float acc[4][4][4];
    #pragma unroll
    for (int i = 0; i < 4; i++)
        #pragma unroll
        for (int j = 0; j < 4; j++)
            #pragma unroll
            for (int r = 0; r < 4; r++) acc[i][j][r] = 0.0f;

    // prologue: stages 0..STAGES-2
    #pragma unroll
    for (int s = 0; s < STAGES - 1; s++) {
        load_stage(s, s);
        CP_COMMIT();
    }

    const int lq = lane >> 2;              // 0..7
    const int lr = lane & 3;               // 0..3

    for (int kt = 0; kt < NK; kt++) {
        CP_WAIT1();
        __syncthreads();

        // issue next stage into the buffer freed last iteration
        if (kt + STAGES - 1 < NK) load_stage((kt + STAGES - 1) % STAGES, kt + STAGES - 1);
        CP_COMMIT();

        const int buf = kt % STAGES;
        const float* As = smem + buf * STAGE_FLOATS;
        const float* Bs = As + TILE_FLOATS;
        const float* Aw = As + (warp_m * 64 + lq) * ROWPAD + lr;
        const float* Bw = Bs + (warp_n * 32 + lq) * ROWPAD + lr;

        #pragma unroll
        for (int ks = 0; ks < 4; ks++) {
            const int k0 = ks << 3;
            uint32_t af[4][4], bf[4][2];
            #pragma unroll
            for (int mt = 0; mt < 4; mt++) {
                const float* p = Aw + mt * 16 * ROWPAD + k0;
                af[mt][0] = __float_as_uint(p[0]);
                af[mt][1] = __float_as_uint(p[8 * ROWPAD]);
                af[mt][2] = __float_as_uint(p[4]);
                af[mt][3] = __float_as_uint(p[8 * ROWPAD + 4]);
            }
            #pragma unroll
            for (int nt = 0; nt < 4; nt++) {
                const float* p = Bw + nt * 8 * ROWPAD + k0;
                bf[nt][0] = __float_as_uint(p[0]);
                bf[nt][1] = __float_as_uint(p[4]);
            }
            #pragma unroll
            for (int mt = 0; mt < 4; mt++)
                #pragma unroll
                for (int nt = 0; nt < 4; nt++)
                    mma_tf32(acc[mt][nt], af[mt], bf[nt]);
        }
        __syncthreads();
    }

    // epilogue: direct global stores (float2 per c-pair)
    const int crow = bm + warp_m * 64 + lq;
    const int ccol = bn + warp_n * 32 + 2 * lr;
    #pragma unroll
    for (int mt = 0; mt < 4; mt++) {
        #pragma unroll
        for (int nt = 0; nt < 4; nt++) {
            float* p0 = C + (size_t)(crow + mt * 16) * OUT_F + ccol + nt * 8;
            float* p1 = p0 + (size_t)8 * OUT_F;
            *reinterpret_cast<float2*>(p0) = make_float2(acc[mt][nt][0], acc[mt][nt][1]);
            *reinterpret_cast<float2*>(p1) = make_float2(acc[mt][nt][2], acc[mt][nt][3]);
        }
    }
}

// ---------------------------------------------------------------------------
extern "C" void kernel_launch(void* const* d_in, const int* in_sizes, int n_in,
                              void* d_out, int out_size) {
    const float* input   = (const float*)d_in[0];
    const int*   trellis = (const int*)  d_in[1];
    const float* tlut    = (const float*)d_in[2];
    const float* scales  = (const float*)d_in[3];
    float*       out     = (float*)d_out;

    float* xbuf; float* wbuf;
    cudaGetSymbolAddress((void**)&xbuf, g_x);
    cudaGetSymbolAddress((void**)&wbuf, g_W);

    // 1) Hadamard rotate activations
    fwht_kernel<<<(M_TOT * (IN_F / 128)) / 8, 256>>>(input, xbuf);
    // 2) Decode weights
    decode_kernel<<<NB, 256>>>(trellis, tlut, scales, wbuf);
    // 3) tf32 mma.sync GEMM
    static bool attr_set = false;
    if (!attr_set) {
        cudaFuncSetAttribute(gemm_mma_kernel,
                             cudaFuncAttributeMaxDynamicSharedMemorySize, SMEM_TOTAL);
        attr_set = true;
    }
    const int nblocks = (M_TOT / BM) * (OUT_F / BN);   // 2048
    gemm_mma_kernel<<<nblocks, 256, SMEM_TOTAL>>>(xbuf, wbuf, out);
}

// round 9
// speedup vs baseline: 4.0985x; 1.1150x over previous
#include <cuda_runtime.h>
#include <cuda_bf16.h>
#include <cstdint>

// ---------------- problem constants ----------------
constexpr int IN_F  = 4096;
constexpr int OUT_F = 4096;
constexpr int M_TOT = 8192;
constexpr int NB    = (OUT_F / 16) * (IN_F / 16);   // 65536 tiles

// ---------------- GEMM tiling ----------------
constexpr int BM = 128;
constexpr int BN = 256;
constexpr int BK = 32;
constexpr int STAGES = 3;
constexpr int NK = IN_F / BK;                   // 128 k-iterations
constexpr int ROWPAD = 40;                      // floats per smem row (conflict-free v2)
constexpr int A_TILE_FLOATS = BM * ROWPAD;      // 5120
constexpr int B_TILE_FLOATS = BN * ROWPAD;      // 10240
constexpr int STAGE_FLOATS  = A_TILE_FLOATS + B_TILE_FLOATS;   // 15360
constexpr int SMEM_TOTAL    = STAGES * STAGE_FLOATS * 4;       // 184320 bytes

// ---------------- scratch (k-interleaved layout: within each 8-k group,
// logical k order stored as [0,4,1,5,2,6,3,7]) ----------------
__device__ float g_x[(size_t)M_TOT * IN_F];
__device__ float g_W[(size_t)OUT_F * IN_F];

// ---------------- helpers ----------------
__device__ __forceinline__ float to_tf32_rn(float x) {
    uint32_t r;
    asm("cvt.rna.tf32.f32 %0, %1;" : "=r"(r) : "f"(x));
    return __uint_as_float(r);
}
__device__ __forceinline__ uint32_t smem_to_u32(const void* p) {
    uint32_t a;
    asm("{ .reg .u64 t; cvta.to.shared.u64 t, %1; cvt.u32.u64 %0, t; }" : "=r"(a) : "l"(p));
    return a;
}
__device__ __forceinline__ void cp_async16(uint32_t dst, const void* src) {
    asm volatile("cp.async.cg.shared.global [%0], [%1], 16;" :: "r"(dst), "l"(src) : "memory");
}
#define CP_COMMIT() asm volatile("cp.async.commit_group;" ::: "memory")
#define CP_WAIT1()  asm volatile("cp.async.wait_group 1;" ::: "memory")

__device__ __forceinline__ void mma_tf32(float* c, const uint32_t* a, const uint32_t* b) {
    asm volatile(
        "mma.sync.aligned.m16n8k8.row.col.f32.tf32.tf32.f32 "
        "{%0,%1,%2,%3}, {%4,%5,%6,%7}, {%8,%9}, {%0,%1,%2,%3};"
        : "+f"(c[0]), "+f"(c[1]), "+f"(c[2]), "+f"(c[3])
        : "r"(a[0]), "r"(a[1]), "r"(a[2]), "r"(a[3]), "r"(b[0]), "r"(b[1]));
}

// ---------------------------------------------------------------------------
// Kernel 1: per-128 FWHT, output rounded to tf32 grid, stored k-interleaved.
// Even/odd lane pairs exchange halves via shfl so float4 stores survive.
// ---------------------------------------------------------------------------
__global__ void __launch_bounds__(256) fwht_kernel(const float* __restrict__ in,
                                                   float* __restrict__ out) {
    const int warp = (blockIdx.x << 3) | (threadIdx.x >> 5);
    const int lane = threadIdx.x & 31;
    const size_t base = (size_t)warp * 128;

    float4 v = reinterpret_cast<const float4*>(in + base)[lane];
    float a = v.x, b = v.y, c = v.z, d = v.w, t;
    t = a; a = a + b; b = t - b;
    t = c; c = c + d; d = t - d;
    t = a; a = a + c; c = t - c;
    t = b; b = b + d; d = t - d;
    #pragma unroll
    for (int mask = 1; mask <= 16; mask <<= 1) {
        float oa = __shfl_xor_sync(0xFFFFFFFFu, a, mask);
        float ob = __shfl_xor_sync(0xFFFFFFFFu, b, mask);
        float oc = __shfl_xor_sync(0xFFFFFFFFu, c, mask);
        float od = __shfl_xor_sync(0xFFFFFFFFu, d, mask);
        const bool hi = (lane & mask) != 0;
        a = hi ? (oa - a) : (a + oa);
        b = hi ? (ob - b) : (b + ob);
        c = hi ? (oc - c) : (c + oc);
        d = hi ? (od - d) : (d + od);
    }
    const float s = 0.08838834764831845f;
    a = to_tf32_rn(a * s); b = to_tf32_rn(b * s);
    c = to_tf32_rn(c * s); d = to_tf32_rn(d * s);

    // k-interleave within each 8-group: lane pair (2g, 2g+1) holds logical
    // k 0..7 of group g; storage order [e.a, o.a, e.b, o.b, e.c, o.c, e.d, o.d]
    const float sa = __shfl_xor_sync(0xFFFFFFFFu, a, 1);
    const float sb = __shfl_xor_sync(0xFFFFFFFFu, b, 1);
    const float sc = __shfl_xor_sync(0xFFFFFFFFu, c, 1);
    const float sd = __shfl_xor_sync(0xFFFFFFFFu, d, 1);
    float4 o = (lane & 1) ? make_float4(sc, c, sd, d)
                          : make_float4(a, sa, b, sb);
    reinterpret_cast<float4*>(out + base)[lane] = o;
}

// ---------------------------------------------------------------------------
// Kernel 2: trellis decode, tf32-rounded, stored k-interleaved.
// ---------------------------------------------------------------------------
__global__ void __launch_bounds__(256) decode_kernel(const int* __restrict__ trellis,
                                                     const float* __restrict__ tlut,
                                                     const float* __restrict__ scales,
                                                     float* __restrict__ W) {
    const int nb = blockIdx.x;
    const int t  = threadIdx.x;

    __shared__ uint32_t w[32];
    if (t < 32) w[t] = (uint32_t)trellis[nb * 32 + t] & 0xFFFFu;
    __syncthreads();

    const int p   = t << 1;
    const int i   = p >> 4;
    const int off = p & 15;
    const uint32_t s = (w[i] << 16) | w[(i + 1) & 31];
    const uint32_t state = (s >> (16 - off)) & 0xFFFFu;

    const float val = tlut[state];

    const int rb = nb >> 8;
    const int cb = nb & 255;
    const int tx = t >> 4;
    const int ty = t & 15;
    const int row = rb * 16 + tx;
    const int col = cb * 16 + ty;

    const float sc = scales[row * (IN_F / 128) + (col >> 7)];
    // k-interleave: within 8-group, pos = 2*(w&3) + (w>>2)
    const int wg = col & 7;
    const int colstore = (col & ~7) | ((wg & 3) << 1) | (wg >> 2);
    W[(size_t)row * IN_F + colstore] = to_tf32_rn(val * sc);
}

// ---------------------------------------------------------------------------
// Kernel 3: tf32 mma.sync GEMM  C[M,N] = A[M,K] @ B[N,K]^T
// 128x256 CTA tile, BK=32, 3-stage cp.async pipeline, 8 warps x (64x64).
// Operands are k-interleaved -> all fragment loads are ld.shared.v2.
// ---------------------------------------------------------------------------
__global__ void __launch_bounds__(256, 1) gemm_mma_kernel(const float* __restrict__ A,
                                                          const float* __restrict__ B,
                                                          float* __restrict__ C) {
    extern __shared__ float smem[];
    const uint32_t sbase = smem_to_u32(smem);

    const int tid  = threadIdx.x;
    const int lane = tid & 31;
    const int warp = tid >> 5;
    const int warp_m = warp >> 2;          // 0..1  -> 64-row slice
    const int warp_n = warp & 3;           // 0..3  -> 64-col slice

    // swizzle: supertiles of 8 m-blocks x 16 n-blocks (~1 wave each)
    const int bid = blockIdx.x;
    const int sm_ = bid >> 7;              // 0..7
    const int w_  = bid & 127;
    const int bm  = ((sm_ << 3) | (w_ & 7)) * BM;
    const int bn  = (w_ >> 3) * BN;

    // global->smem: 16B chunks
    const int lrow = tid >> 3;             // 0..31
    const int lcol = (tid & 7) << 2;       // 0,4,...,28

    const float* Ag = A + (size_t)(bm + lrow) * IN_F + lcol;
    const float* Bg = B + (size_t)(bn + lrow) * IN_F + lcol;

    auto load_stage = [&](int buf, int kt) {
        const uint32_t sA = sbase + (uint32_t)(buf * STAGE_FLOATS) * 4;
        const uint32_t sB = sA + (uint32_t)A_TILE_FLOATS * 4;
        const int koff = kt * BK;
        #pragma unroll
        for (int r = 0; r < 4; r++)
            cp_async16(sA + (uint32_t)((lrow + (r << 5)) * ROWPAD + lcol) * 4,
                       Ag + (size_t)(r << 5) * IN_F + koff);
        #pragma unroll
        for (int r = 0; r < 8; r++)
            cp_async16(sB + (uint32_t)((lrow + (r << 5)) * ROWPAD + lcol) * 4,
                       Bg + (size_t)(r << 5) * IN_F + koff);
    };

    float acc[4][8][4];
    #pragma unroll
    for (int i = 0; i < 4; i++)
        #pragma unroll
        for (int j = 0; j < 8; j++)
            #pragma unroll
            for (int r = 0; r < 4; r++) acc[i][j][r] = 0.0f;

    #pragma unroll
    for (int s = 0; s < STAGES - 1; s++) {
        load_stage(s, s);
        CP_COMMIT();
    }

    const int lq = lane >> 2;              // 0..7
    const int lr = lane & 3;               // 0..3

    for (int kt = 0; kt < NK; kt++) {
        CP_WAIT1();
        __syncthreads();

        if (kt + STAGES - 1 < NK) load_stage((kt + STAGES - 1) % STAGES, kt + STAGES - 1);
        CP_COMMIT();

        const int buf = kt % STAGES;
        const float* As = smem + buf * STAGE_FLOATS;
        const float* Bs = As + A_TILE_FLOATS;
        const float* Aw = As + (warp_m * 64 + lq) * ROWPAD + 2 * lr;
        const float* Bw = Bs + (warp_n * 64 + lq) * ROWPAD + 2 * lr;

        #pragma unroll
        for (int ks = 0; ks < 4; ks++) {
            const int k0 = ks << 3;
            uint32_t af[4][4], bf[8][2];
            #pragma unroll
            for (int mt = 0; mt < 4; mt++) {
                float2 lo = *reinterpret_cast<const float2*>(Aw + (mt * 16) * ROWPAD + k0);
                float2 hi = *reinterpret_cast<const float2*>(Aw + (mt * 16 + 8) * ROWPAD + k0);
                af[mt][0] = __float_as_uint(lo.x);   // (row lq,   k lr)
                af[mt][1] = __float_as_uint(hi.x);   // (row lq+8, k lr)
                af[mt][2] = __float_as_uint(lo.y);   // (row lq,   k lr+4)
                af[mt][3] = __float_as_uint(hi.y);   // (row lq+8, k lr+4)
            }
            #pragma unroll
            for (int nt = 0; nt < 8; nt++) {
                float2 b = *reinterpret_cast<const float2*>(Bw + (nt * 8) * ROWPAD + k0);
                bf[nt][0] = __float_as_uint(b.x);
                bf[nt][1] = __float_as_uint(b.y);
            }
            #pragma unroll
            for (int mt = 0; mt < 4; mt++)
                #pragma unroll
                for (int nt = 0; nt < 8; nt++)
                    mma_tf32(acc[mt][nt], af[mt], bf[nt]);
        }
    }

    // epilogue
    const int crow = bm + warp_m * 64 + lq;
    const int ccol = bn + warp_n * 64 + 2 * lr;
    #pragma unroll
    for (int mt = 0; mt < 4; mt++) {
        #pragma unroll
        for (int nt = 0; nt < 8; nt++) {
            float* p0 = C + (size_t)(crow + mt * 16) * OUT_F + ccol + nt * 8;
            float* p1 = p0 + (size_t)8 * OUT_F;
            *reinterpret_cast<float2*>(p0) = make_float2(acc[mt][nt][0], acc[mt][nt][1]);
            *reinterpret_cast<float2*>(p1) = make_float2(acc[mt][nt][2], acc[mt][nt][3]);
        }
    }
}

// ---------------------------------------------------------------------------
extern "C" void kernel_launch(void* const* d_in, const int* in_sizes, int n_in,
                              void* d_out, int out_size) {
    const float* input   = (const float*)d_in[0];
    const int*   trellis = (const int*)  d_in[1];
    const float* tlut    = (const float*)d_in[2];
    const float* scales  = (const float*)d_in[3];
    float*       out     = (float*)d_out;

    float* xbuf; float* wbuf;
    cudaGetSymbolAddress((void**)&xbuf, g_x);
    cudaGetSymbolAddress((void**)&wbuf, g_W);

    // 1) Hadamard rotate activations
    fwht_kernel<<<(M_TOT * (IN_F / 128)) / 8, 256>>>(input, xbuf);
    // 2) Decode weights
    decode_kernel<<<NB, 256>>>(trellis, tlut, scales, wbuf);
    // 3) tf32 mma.sync GEMM
    static bool attr_set = false;
    if (!attr_set) {
        cudaFuncSetAttribute(gemm_mma_kernel,
                             cudaFuncAttributeMaxDynamicSharedMemorySize, SMEM_TOTAL);
        attr_set = true;
    }
    const int nblocks = (M_TOT / BM) * (OUT_F / BN);   // 1024
    gemm_mma_kernel<<<nblocks, 256, SMEM_TOTAL>>>(xbuf, wbuf, out);
}